// round 14
// baseline (speedup 1.0000x reference)
#include <cuda_runtime.h>
#include <cuda_fp16.h>
#include <cstdint>
#include <cstddef>

#define BB 32
#define NN 4096
#define CC 768
#define KK 8
#define MM (BB * NN)   // 131072 rows

// Scratch (__device__ globals; allocation-free rule)
__device__ __half g_A[(size_t)MM * CC];     // LN(x), fp16
__device__ __half g_W1T[(size_t)CC * CC];   // W1^T ([n][k], k contiguous), fp16
__device__ float g_logits[(size_t)MM * KK];
__device__ float g_mx[BB * KK];             // softmax row max per (b,k)
__device__ float g_inv[BB * KK];            // 1/sum per (b,k)

// ---------------------------------------------------------------------------
// PTX helpers (plain-sm_103-legal: mma.sync, ldmatrix, cp.async)
// ---------------------------------------------------------------------------
__device__ __forceinline__ uint32_t smem_to_u32(const void* p) {
    uint32_t a;
    asm("{ .reg .u64 t; cvta.to.shared.u64 t, %1; cvt.u32.u64 %0, t; }"
        : "=r"(a) : "l"(p));
    return a;
}
#define CP_ASYNC16(dst, src) \
    asm volatile("cp.async.cg.shared.global [%0], [%1], 16;" :: "r"(dst), "l"(src))
#define CP_COMMIT() asm volatile("cp.async.commit_group;" ::: "memory")
#define CP_WAIT(n)  asm volatile("cp.async.wait_group %0;" :: "n"(n) : "memory")

__device__ __forceinline__ void ldsm_x4(uint32_t (&r)[4], uint32_t addr) {
    asm volatile("ldmatrix.sync.aligned.m8n8.x4.shared.b16 {%0,%1,%2,%3}, [%4];"
        : "=r"(r[0]), "=r"(r[1]), "=r"(r[2]), "=r"(r[3]) : "r"(addr));
}
__device__ __forceinline__ void mma_f16(float (&d)[4], const uint32_t (&a)[4],
                                        const uint32_t* b) {
    asm volatile(
        "mma.sync.aligned.m16n8k16.row.col.f32.f16.f16.f32 "
        "{%0,%1,%2,%3}, {%4,%5,%6,%7}, {%8,%9}, {%0,%1,%2,%3};"
        : "+f"(d[0]), "+f"(d[1]), "+f"(d[2]), "+f"(d[3])
        : "r"(a[0]), "r"(a[1]), "r"(a[2]), "r"(a[3]), "r"(b[0]), "r"(b[1]));
}

__device__ __forceinline__ float gelu_exact(float v) {
    return 0.5f * v * (1.0f + erff(v * 0.70710678118654752440f));
}

// ---------------------------------------------------------------------------
// Kernel 1: fused LN stats + fp16 convert. One warp per row.
// ---------------------------------------------------------------------------
__global__ __launch_bounds__(256)
void ln_convert_kernel(const float* __restrict__ x,
                       const float* __restrict__ gamma,
                       const float* __restrict__ beta) {
    __shared__ float gs[CC], bs[CC];
    const int tid = threadIdx.x;
    for (int i = tid; i < CC; i += 256) { gs[i] = gamma[i]; bs[i] = beta[i]; }
    __syncthreads();

    const int row  = blockIdx.x * 8 + (tid >> 5);
    const int lane = tid & 31;
    const float4* r = (const float4*)(x + (size_t)row * CC);
    float s = 0.f, ss = 0.f;
    #pragma unroll
    for (int i = lane; i < CC / 4; i += 32) {
        float4 v = r[i];
        s  += v.x + v.y + v.z + v.w;
        ss += v.x * v.x + v.y * v.y + v.z * v.z + v.w * v.w;
    }
    #pragma unroll
    for (int o = 16; o; o >>= 1) {
        s  += __shfl_xor_sync(0xffffffffu, s,  o);
        ss += __shfl_xor_sync(0xffffffffu, ss, o);
    }
    const float mu = s * (1.0f / CC);
    const float rs = rsqrtf(ss * (1.0f / CC) - mu * mu + 1e-5f);

    __half* ap = g_A + (size_t)row * CC;
    #pragma unroll
    for (int i = lane; i < CC / 4; i += 32) {
        float4 v = r[i];
        float y[4] = {v.x, v.y, v.z, v.w};
        union { __half h[4]; uint2 u; } hu;
        #pragma unroll
        for (int j = 0; j < 4; ++j)
            hu.h[j] = __float2half((y[j] - mu) * rs * gs[i * 4 + j] + bs[i * 4 + j]);
        *(uint2*)(ap + i * 4) = hu.u;
    }
}

// ---------------------------------------------------------------------------
// Kernel 2: W1 transpose + fp16 convert. out[n][k] = fp16(W1[k][n]).
// ---------------------------------------------------------------------------
__global__ __launch_bounds__(256)
void w1_convert_kernel(const float* __restrict__ W1) {
    __shared__ float t[32][33];
    const int tx = threadIdx.x, ty = threadIdx.y;    // 32x8
    const int bn = blockIdx.x * 32, bk = blockIdx.y * 32;
    #pragma unroll
    for (int i = 0; i < 4; ++i)
        t[ty + i * 8][tx] = W1[(size_t)(bk + ty + i * 8) * CC + bn + tx];
    __syncthreads();
    #pragma unroll
    for (int i = 0; i < 4; ++i) {
        const int n = bn + ty + i * 8, k = bk + tx;
        g_W1T[(size_t)n * CC + k] = __float2half(t[tx][ty + i * 8]);
    }
}

// ---------------------------------------------------------------------------
// Kernel 3: zero logits (keeps GEMM in ncu's capture slot 4).
// ---------------------------------------------------------------------------
__global__ __launch_bounds__(256)
void zero_logits_kernel() {
    ((float4*)g_logits)[(size_t)blockIdx.x * 256 + threadIdx.x] =
        make_float4(0.f, 0.f, 0.f, 0.f);
}

// ---------------------------------------------------------------------------
// Kernel 4: fp16 mma.sync GEMM  logits += GELU(LN(x)@W1 + b1) @ W2
// CTA tile 128x128, 4 warps (2x2), warp 64x64, KC=64, 3-stage pipeline,
// 2 CTAs/SM. Rows of 128B; swizzle: seg ^= row&7.
// ---------------------------------------------------------------------------
#define KC      64
#define NCH     12                 // 768/64
#define TILE_B  16384              // 128 rows x 128 bytes
#define BUFSZ   (2 * TILE_B)       // A | B = 32KB
#define OFF_B   TILE_B
#define NSTAGE  3
#define SM_W2   (NSTAGE * BUFSZ)   // 98304
#define SM_B1   (SM_W2 + 4096)
#define SM_TOTAL (SM_B1 + 512 + 1024)
#define NT      128                // threads per CTA

__device__ __forceinline__ uint32_t swz(int row, int seg) {
    return (uint32_t)(row * 128) + (uint32_t)(((seg ^ (row & 7)) & 7) << 4);
}

__device__ __forceinline__ void load_tile_cp(uint32_t dst, const __half* src,
                                             int tid) {
    // 128 rows x 64 fp16 (128B rows) = 1024 x 16B, 8 per thread
    #pragma unroll
    for (int j = 0; j < 8; ++j) {
        const int c = tid + j * NT;
        const int row = c >> 3, seg = c & 7;
        CP_ASYNC16(dst + swz(row, seg), src + (size_t)row * CC + seg * 8);
    }
}

__global__ __launch_bounds__(NT, 2)
void gemm_kernel(const float* __restrict__ W2, const float* __restrict__ b1) {
    extern __shared__ __align__(16) char smraw[];
    const uint32_t sbraw = smem_to_u32(smraw);
    const uint32_t sb = (sbraw + 1023u) & ~1023u;
    char* sm = smraw + (sb - sbraw);
    float* W2s = (float*)(sm + SM_W2);
    float* b1s = (float*)(sm + SM_B1);

    const int tid = threadIdx.x;
    const int wid = tid >> 5;
    const int lid = tid & 31;
    const int warp_m = wid & 1;          // 2 along M (64 rows each)
    const int warp_n = wid >> 1;         // 2 along N (64 cols each)
    const int n0 = blockIdx.x * 128;
    const int r0 = blockIdx.y * 128;

    const __half* pA = g_A   + (size_t)r0 * CC;
    const __half* pB = g_W1T + (size_t)n0 * CC;

    for (int i = tid; i < 1024; i += NT) W2s[i] = W2[(size_t)n0 * KK + i];
    if (tid < 128) b1s[tid] = b1[n0 + tid];

    // prologue: stages 0, 1
    #pragma unroll
    for (int st = 0; st < 2; ++st) {
        const uint32_t bb = sb + st * BUFSZ;
        const int k0 = st * KC;
        load_tile_cp(bb,         pA + k0, tid);
        load_tile_cp(bb + OFF_B, pB + k0, tid);
        CP_COMMIT();
    }

    float acc[4][8][4];                  // mf(4 x m16) x nf(8 x n8) x 4
    #pragma unroll
    for (int mf = 0; mf < 4; ++mf)
        #pragma unroll
        for (int nf = 0; nf < 8; ++nf)
            #pragma unroll
            for (int r = 0; r < 4; ++r) acc[mf][nf][r] = 0.f;

    const int a_row = warp_m * 64 + (lid & 15);                       // + mf*16
    const int a_seg = lid >> 4;                                       // + ks*2
    const int b_mat = lid >> 3;
    const int b_row = warp_n * 64 + ((b_mat >> 1) << 3) + (lid & 7);  // + np*16
    const int b_seg = b_mat & 1;                                      // + ks*2

    int stage = 0;
    for (int i = 0; i < NCH; ++i) {
        if (i < NCH - 1) CP_WAIT(1); else CP_WAIT(0);
        __syncthreads();

        // prefetch stage i+2 (overwrites buffer of stage i-1; safe after sync)
        if (i + 2 < NCH) {
            int st2 = stage + 2; if (st2 >= NSTAGE) st2 -= NSTAGE;
            const uint32_t bb = sb + st2 * BUFSZ;
            const int k0 = (i + 2) * KC;
            load_tile_cp(bb,         pA + k0, tid);
            load_tile_cp(bb + OFF_B, pB + k0, tid);
            CP_COMMIT();
        }

        const uint32_t bb = sb + stage * BUFSZ;
        #pragma unroll
        for (int ks = 0; ks < 4; ++ks) {
            uint32_t af[4][4];
            #pragma unroll
            for (int mf = 0; mf < 4; ++mf)
                ldsm_x4(af[mf], bb + swz(a_row + mf * 16, a_seg + ks * 2));
            #pragma unroll
            for (int np = 0; np < 4; ++np) {
                uint32_t bf[4];
                ldsm_x4(bf, bb + OFF_B + swz(b_row + np * 16, b_seg + ks * 2));
                #pragma unroll
                for (int mf = 0; mf < 4; ++mf) {
                    mma_f16(acc[mf][np * 2 + 0], af[mf], bf + 0);
                    mma_f16(acc[mf][np * 2 + 1], af[mf], bf + 2);
                }
            }
        }
        ++stage; if (stage == NSTAGE) stage = 0;
    }
    __syncthreads();

    // ---------------- Epilogue: +b1, GELU, fold W2, reduce ----------------
    float* logits_s = (float*)sm;        // reuse pipeline smem: 128x8 f32
    for (int i = tid; i < 1024; i += NT) logits_s[i] = 0.f;
    __syncthreads();

    const int qr = lid >> 2, qc = lid & 3;
    #pragma unroll
    for (int mf = 0; mf < 4; ++mf) {
        float lg[2][8];
        #pragma unroll
        for (int h = 0; h < 2; ++h)
            #pragma unroll
            for (int k = 0; k < 8; ++k) lg[h][k] = 0.f;

        #pragma unroll
        for (int nf = 0; nf < 8; ++nf) {
            const int colb = warp_n * 64 + nf * 8 + qc * 2;
            #pragma unroll
            for (int r = 0; r < 4; ++r) {
                const int c = colb + (r & 1);
                const float v = acc[mf][nf][r] + b1s[c];
                const float hh = gelu_exact(v);
                const float* w = &W2s[c * 8];
                float* l = lg[r >> 1];
                #pragma unroll
                for (int k = 0; k < 8; ++k) l[k] = fmaf(hh, w[k], l[k]);
            }
        }
        const int rA = warp_m * 64 + mf * 16 + qr;
        #pragma unroll
        for (int k = 0; k < 8; ++k) {
            atomicAdd(&logits_s[rA * 8 + k],       lg[0][k]);
            atomicAdd(&logits_s[(rA + 8) * 8 + k], lg[1][k]);
        }
    }
    __syncthreads();

    for (int i = tid; i < 1024; i += NT) {
        const int r = i >> 3, k = i & 7;
        atomicAdd(&g_logits[(size_t)(r0 + r) * KK + k], logits_s[i]);
    }
}

// ---------------------------------------------------------------------------
// Kernel 5: softmax stats per (b,k): row max and 1/sum(exp).
// ---------------------------------------------------------------------------
__global__ __launch_bounds__(256)
void softmax_stats_kernel() {
    __shared__ float red[8];
    __shared__ float bcast;
    const int bk = blockIdx.x;
    const int b  = bk >> 3;
    const int kk = bk & 7;
    const int tid = threadIdx.x;
    const float* base = g_logits + (size_t)b * NN * KK + kk;

    float v[16];
    float mx = -1e30f;
    #pragma unroll
    for (int i = 0; i < 16; ++i) {
        v[i] = base[(size_t)(i * 256 + tid) * KK];
        mx = fmaxf(mx, v[i]);
    }
    #pragma unroll
    for (int o = 16; o; o >>= 1) mx = fmaxf(mx, __shfl_xor_sync(0xffffffffu, mx, o));
    if ((tid & 31) == 0) red[tid >> 5] = mx;
    __syncthreads();
    if (tid < 32) {
        float m = (tid < 8) ? red[tid] : -1e30f;
        #pragma unroll
        for (int o = 4; o; o >>= 1) m = fmaxf(m, __shfl_xor_sync(0xffffffffu, m, o));
        if (tid == 0) bcast = m;
    }
    __syncthreads();
    mx = bcast;

    float s = 0.f;
    #pragma unroll
    for (int i = 0; i < 16; ++i) s += __expf(v[i] - mx);
    #pragma unroll
    for (int o = 16; o; o >>= 1) s += __shfl_xor_sync(0xffffffffu, s, o);
    __syncthreads();
    if ((tid & 31) == 0) red[tid >> 5] = s;
    __syncthreads();
    if (tid < 32) {
        float t = (tid < 8) ? red[tid] : 0.f;
        #pragma unroll
        for (int o = 4; o; o >>= 1) t += __shfl_xor_sync(0xffffffffu, t, o);
        if (tid == 0) { g_mx[bk] = mx; g_inv[bk] = 1.0f / t; }
    }
}

// ---------------------------------------------------------------------------
// Kernel 6: out[b,k,c] = sum_n softmax(logits)[b,n,k] * x[b,n,c]
// ---------------------------------------------------------------------------
__global__ __launch_bounds__(256)
void pool_kernel(const float* __restrict__ x, float* __restrict__ out) {
    __shared__ float attn_s[512][8];     // 16 KB
    __shared__ float smx[8], sinv[8];
    const int nc = blockIdx.x;           // 0..7
    const int ct = blockIdx.y;           // 0..2
    const int b  = blockIdx.z;           // 0..31
    const int n0 = nc * 512;
    const int tid = threadIdx.x;

    if (tid < 8) { smx[tid] = g_mx[b * 8 + tid]; sinv[tid] = g_inv[b * 8 + tid]; }
    __syncthreads();

    const float* lp = g_logits + ((size_t)b * NN + n0) * KK;
    for (int i = tid; i < 512 * 8; i += 256) {
        const int k = i & 7;
        attn_s[i >> 3][k] = __expf(lp[i] - smx[k]) * sinv[k];
    }
    __syncthreads();

    const int c = ct * 256 + tid;
    const float* xp = x + ((size_t)b * NN + n0) * CC + c;
    float acc[8];
    #pragma unroll
    for (int kk = 0; kk < 8; ++kk) acc[kk] = 0.f;

    for (int nb = 0; nb < 512; nb += 8) {
        float xv[8];
        #pragma unroll
        for (int u = 0; u < 8; ++u)
            xv[u] = xp[(size_t)(nb + u) * CC];
        #pragma unroll
        for (int u = 0; u < 8; ++u) {
            float4 a0 = *(const float4*)(&attn_s[nb + u][0]);
            float4 a1 = *(const float4*)(&attn_s[nb + u][4]);
            acc[0] = fmaf(a0.x, xv[u], acc[0]);
            acc[1] = fmaf(a0.y, xv[u], acc[1]);
            acc[2] = fmaf(a0.z, xv[u], acc[2]);
            acc[3] = fmaf(a0.w, xv[u], acc[3]);
            acc[4] = fmaf(a1.x, xv[u], acc[4]);
            acc[5] = fmaf(a1.y, xv[u], acc[5]);
            acc[6] = fmaf(a1.z, xv[u], acc[6]);
            acc[7] = fmaf(a1.w, xv[u], acc[7]);
        }
    }
    #pragma unroll
    for (int kk = 0; kk < 8; ++kk)
        atomicAdd(&out[((size_t)b * KK + kk) * CC + c], acc[kk]);
}

// ---------------------------------------------------------------------------
extern "C" void kernel_launch(void* const* d_in, const int* in_sizes, int n_in,
                              void* d_out, int out_size) {
    const float* x     = (const float*)d_in[0];
    const float* gamma = (const float*)d_in[1];
    const float* beta  = (const float*)d_in[2];
    const float* W1    = (const float*)d_in[3];
    const float* b1    = (const float*)d_in[4];
    const float* W2    = (const float*)d_in[5];
    // b2 (d_in[6]) unused: constant over tokens -> cancels in softmax
    float* out = (float*)d_out;

    cudaMemsetAsync(out, 0, (size_t)out_size * sizeof(float));
    ln_convert_kernel<<<MM / 8, 256>>>(x, gamma, beta);                     // 1
    w1_convert_kernel<<<dim3(CC / 32, CC / 32), dim3(32, 8)>>>(W1);         // 2
    zero_logits_kernel<<<(MM * KK) / 1024, 256>>>();                        // 3
    cudaFuncSetAttribute(gemm_kernel, cudaFuncAttributeMaxDynamicSharedMemorySize, SM_TOTAL);
    gemm_kernel<<<dim3(6, MM / 128), NT, SM_TOTAL>>>(W2, b1);               // 4 (profiled)
    softmax_stats_kernel<<<BB * KK, 256>>>();                               // 5
    pool_kernel<<<dim3(8, 3, 32), 256>>>(x, out);                           // 6
}

// round 15
// speedup vs baseline: 1.0047x; 1.0047x over previous
#include <cuda_runtime.h>
#include <cuda_fp16.h>
#include <cstdint>
#include <cstddef>

#define BB 32
#define NN 4096
#define CC 768
#define KK 8
#define MM (BB * NN)   // 131072 rows

// Scratch (__device__ globals; allocation-free rule)
__device__ __half g_A[(size_t)MM * CC];     // LN(x), fp16
__device__ __half g_W1T[(size_t)CC * CC];   // W1^T ([n][k], k contiguous), fp16
__device__ float g_logits[(size_t)MM * KK];
__device__ float g_mx[BB * KK];             // softmax row max per (b,k)
__device__ float g_inv[BB * KK];            // 1/sum per (b,k)

// ---------------------------------------------------------------------------
// PTX helpers (plain-sm_103-legal: mma.sync, ldmatrix, cp.async)
// ---------------------------------------------------------------------------
__device__ __forceinline__ uint32_t smem_to_u32(const void* p) {
    uint32_t a;
    asm("{ .reg .u64 t; cvta.to.shared.u64 t, %1; cvt.u32.u64 %0, t; }"
        : "=r"(a) : "l"(p));
    return a;
}
#define CP_ASYNC16(dst, src) \
    asm volatile("cp.async.cg.shared.global [%0], [%1], 16;" :: "r"(dst), "l"(src))
#define CP_COMMIT() asm volatile("cp.async.commit_group;" ::: "memory")
#define CP_WAIT(n)  asm volatile("cp.async.wait_group %0;" :: "n"(n) : "memory")

__device__ __forceinline__ void ldsm_x4(uint32_t (&r)[4], uint32_t addr) {
    asm volatile("ldmatrix.sync.aligned.m8n8.x4.shared.b16 {%0,%1,%2,%3}, [%4];"
        : "=r"(r[0]), "=r"(r[1]), "=r"(r[2]), "=r"(r[3]) : "r"(addr));
}
__device__ __forceinline__ void mma_f16(float (&d)[4], const uint32_t (&a)[4],
                                        const uint32_t* b) {
    asm volatile(
        "mma.sync.aligned.m16n8k16.row.col.f32.f16.f16.f32 "
        "{%0,%1,%2,%3}, {%4,%5,%6,%7}, {%8,%9}, {%0,%1,%2,%3};"
        : "+f"(d[0]), "+f"(d[1]), "+f"(d[2]), "+f"(d[3])
        : "r"(a[0]), "r"(a[1]), "r"(a[2]), "r"(a[3]), "r"(b[0]), "r"(b[1]));
}

__device__ __forceinline__ float gelu_exact(float v) {
    return 0.5f * v * (1.0f + erff(v * 0.70710678118654752440f));
}

// ---------------------------------------------------------------------------
// Kernel 1: fused LN stats + fp16 convert. One warp per row.
// ---------------------------------------------------------------------------
__global__ __launch_bounds__(256)
void ln_convert_kernel(const float* __restrict__ x,
                       const float* __restrict__ gamma,
                       const float* __restrict__ beta) {
    __shared__ float gs[CC], bs[CC];
    const int tid = threadIdx.x;
    for (int i = tid; i < CC; i += 256) { gs[i] = gamma[i]; bs[i] = beta[i]; }
    __syncthreads();

    const int row  = blockIdx.x * 8 + (tid >> 5);
    const int lane = tid & 31;
    const float4* r = (const float4*)(x + (size_t)row * CC);
    float s = 0.f, ss = 0.f;
    #pragma unroll
    for (int i = lane; i < CC / 4; i += 32) {
        float4 v = r[i];
        s  += v.x + v.y + v.z + v.w;
        ss += v.x * v.x + v.y * v.y + v.z * v.z + v.w * v.w;
    }
    #pragma unroll
    for (int o = 16; o; o >>= 1) {
        s  += __shfl_xor_sync(0xffffffffu, s,  o);
        ss += __shfl_xor_sync(0xffffffffu, ss, o);
    }
    const float mu = s * (1.0f / CC);
    const float rs = rsqrtf(ss * (1.0f / CC) - mu * mu + 1e-5f);

    __half* ap = g_A + (size_t)row * CC;
    #pragma unroll
    for (int i = lane; i < CC / 4; i += 32) {
        float4 v = r[i];
        float y[4] = {v.x, v.y, v.z, v.w};
        union { __half h[4]; uint2 u; } hu;
        #pragma unroll
        for (int j = 0; j < 4; ++j)
            hu.h[j] = __float2half((y[j] - mu) * rs * gs[i * 4 + j] + bs[i * 4 + j]);
        *(uint2*)(ap + i * 4) = hu.u;
    }
}

// ---------------------------------------------------------------------------
// Kernel 2: W1 transpose + fp16 convert. out[n][k] = fp16(W1[k][n]).
// ---------------------------------------------------------------------------
__global__ __launch_bounds__(256)
void w1_convert_kernel(const float* __restrict__ W1) {
    __shared__ float t[32][33];
    const int tx = threadIdx.x, ty = threadIdx.y;    // 32x8
    const int bn = blockIdx.x * 32, bk = blockIdx.y * 32;
    #pragma unroll
    for (int i = 0; i < 4; ++i)
        t[ty + i * 8][tx] = W1[(size_t)(bk + ty + i * 8) * CC + bn + tx];
    __syncthreads();
    #pragma unroll
    for (int i = 0; i < 4; ++i) {
        const int n = bn + ty + i * 8, k = bk + tx;
        g_W1T[(size_t)n * CC + k] = __float2half(t[tx][ty + i * 8]);
    }
}

// ---------------------------------------------------------------------------
// Kernel 3: zero logits (keeps GEMM in ncu's capture slot 4).
// ---------------------------------------------------------------------------
__global__ __launch_bounds__(256)
void zero_logits_kernel() {
    ((float4*)g_logits)[(size_t)blockIdx.x * 256 + threadIdx.x] =
        make_float4(0.f, 0.f, 0.f, 0.f);
}

// ---------------------------------------------------------------------------
// Kernel 4: fp16 mma.sync GEMM  logits += GELU(LN(x)@W1 + b1) @ W2
// CTA tile 128x128, 4 warps (2x2), warp 64x64, KC=64, 3-stage pipeline,
// 2 CTAs/SM. Rows of 128B; swizzle: seg ^= row&7.
// ---------------------------------------------------------------------------
#define KC      64
#define NCH     12                 // 768/64
#define TILE_B  16384              // 128 rows x 128 bytes
#define BUFSZ   (2 * TILE_B)       // A | B = 32KB
#define OFF_B   TILE_B
#define NSTAGE  3
#define SM_W2   (NSTAGE * BUFSZ)   // 98304
#define SM_B1   (SM_W2 + 4096)
#define SM_TOTAL (SM_B1 + 512 + 1024)
#define NT      128                // threads per CTA

__device__ __forceinline__ uint32_t swz(int row, int seg) {
    return (uint32_t)(row * 128) + (uint32_t)(((seg ^ (row & 7)) & 7) << 4);
}

__device__ __forceinline__ void load_tile_cp(uint32_t dst, const __half* src,
                                             int tid) {
    // 128 rows x 64 fp16 (128B rows) = 1024 x 16B, 8 per thread
    #pragma unroll
    for (int j = 0; j < 8; ++j) {
        const int c = tid + j * NT;
        const int row = c >> 3, seg = c & 7;
        CP_ASYNC16(dst + swz(row, seg), src + (size_t)row * CC + seg * 8);
    }
}

__global__ __launch_bounds__(NT, 2)
void gemm_kernel(const float* __restrict__ W2, const float* __restrict__ b1) {
    extern __shared__ __align__(16) char smraw[];
    const uint32_t sbraw = smem_to_u32(smraw);
    const uint32_t sb = (sbraw + 1023u) & ~1023u;
    char* sm = smraw + (sb - sbraw);
    float* W2s = (float*)(sm + SM_W2);
    float* b1s = (float*)(sm + SM_B1);

    const int tid = threadIdx.x;
    const int wid = tid >> 5;
    const int lid = tid & 31;
    const int warp_m = wid & 1;          // 2 along M (64 rows each)
    const int warp_n = wid >> 1;         // 2 along N (64 cols each)
    const int n0 = blockIdx.x * 128;
    const int r0 = blockIdx.y * 128;

    const __half* pA = g_A   + (size_t)r0 * CC;
    const __half* pB = g_W1T + (size_t)n0 * CC;

    for (int i = tid; i < 1024; i += NT) W2s[i] = W2[(size_t)n0 * KK + i];
    if (tid < 128) b1s[tid] = b1[n0 + tid];

    // prologue: stages 0, 1
    #pragma unroll
    for (int st = 0; st < 2; ++st) {
        const uint32_t bb = sb + st * BUFSZ;
        const int k0 = st * KC;
        load_tile_cp(bb,         pA + k0, tid);
        load_tile_cp(bb + OFF_B, pB + k0, tid);
        CP_COMMIT();
    }

    float acc[4][8][4];                  // mf(4 x m16) x nf(8 x n8) x 4
    #pragma unroll
    for (int mf = 0; mf < 4; ++mf)
        #pragma unroll
        for (int nf = 0; nf < 8; ++nf)
            #pragma unroll
            for (int r = 0; r < 4; ++r) acc[mf][nf][r] = 0.f;

    const int a_row = warp_m * 64 + (lid & 15);                       // + mf*16
    const int a_seg = lid >> 4;                                       // + ks*2
    const int b_mat = lid >> 3;
    const int b_row = warp_n * 64 + ((b_mat >> 1) << 3) + (lid & 7);  // + np*16
    const int b_seg = b_mat & 1;                                      // + ks*2

    int stage = 0;
    for (int i = 0; i < NCH; ++i) {
        if (i < NCH - 1) CP_WAIT(1); else CP_WAIT(0);
        __syncthreads();

        // prefetch stage i+2 (overwrites buffer of stage i-1; safe after sync)
        if (i + 2 < NCH) {
            int st2 = stage + 2; if (st2 >= NSTAGE) st2 -= NSTAGE;
            const uint32_t bb = sb + st2 * BUFSZ;
            const int k0 = (i + 2) * KC;
            load_tile_cp(bb,         pA + k0, tid);
            load_tile_cp(bb + OFF_B, pB + k0, tid);
            CP_COMMIT();
        }

        const uint32_t bb = sb + stage * BUFSZ;
        #pragma unroll
        for (int ks = 0; ks < 4; ++ks) {
            uint32_t af[4][4];
            #pragma unroll
            for (int mf = 0; mf < 4; ++mf)
                ldsm_x4(af[mf], bb + swz(a_row + mf * 16, a_seg + ks * 2));
            #pragma unroll
            for (int np = 0; np < 4; ++np) {
                uint32_t bf[4];
                ldsm_x4(bf, bb + OFF_B + swz(b_row + np * 16, b_seg + ks * 2));
                #pragma unroll
                for (int mf = 0; mf < 4; ++mf) {
                    mma_f16(acc[mf][np * 2 + 0], af[mf], bf + 0);
                    mma_f16(acc[mf][np * 2 + 1], af[mf], bf + 2);
                }
            }
        }
        ++stage; if (stage == NSTAGE) stage = 0;
    }
    __syncthreads();

    // ---------------- Epilogue: +b1, GELU, fold W2, reduce ----------------
    float* logits_s = (float*)sm;        // reuse pipeline smem: 128x8 f32
    for (int i = tid; i < 1024; i += NT) logits_s[i] = 0.f;
    __syncthreads();

    const int qr = lid >> 2, qc = lid & 3;
    #pragma unroll
    for (int mf = 0; mf < 4; ++mf) {
        float lg[2][8];
        #pragma unroll
        for (int h = 0; h < 2; ++h)
            #pragma unroll
            for (int k = 0; k < 8; ++k) lg[h][k] = 0.f;

        #pragma unroll
        for (int nf = 0; nf < 8; ++nf) {
            const int colb = warp_n * 64 + nf * 8 + qc * 2;
            #pragma unroll
            for (int r = 0; r < 4; ++r) {
                const int c = colb + (r & 1);
                const float v = acc[mf][nf][r] + b1s[c];
                const float hh = gelu_exact(v);
                const float* w = &W2s[c * 8];
                float* l = lg[r >> 1];
                #pragma unroll
                for (int k = 0; k < 8; ++k) l[k] = fmaf(hh, w[k], l[k]);
            }
        }
        const int rA = warp_m * 64 + mf * 16 + qr;
        #pragma unroll
        for (int k = 0; k < 8; ++k) {
            atomicAdd(&logits_s[rA * 8 + k],       lg[0][k]);
            atomicAdd(&logits_s[(rA + 8) * 8 + k], lg[1][k]);
        }
    }
    __syncthreads();

    for (int i = tid; i < 1024; i += NT) {
        const int r = i >> 3, k = i & 7;
        atomicAdd(&g_logits[(size_t)(r0 + r) * KK + k], logits_s[i]);
    }
}

// ---------------------------------------------------------------------------
// Kernel 5: softmax stats per (b,k): row max and 1/sum(exp).
// ---------------------------------------------------------------------------
__global__ __launch_bounds__(256)
void softmax_stats_kernel() {
    __shared__ float red[8];
    __shared__ float bcast;
    const int bk = blockIdx.x;
    const int b  = bk >> 3;
    const int kk = bk & 7;
    const int tid = threadIdx.x;
    const float* base = g_logits + (size_t)b * NN * KK + kk;

    float v[16];
    float mx = -1e30f;
    #pragma unroll
    for (int i = 0; i < 16; ++i) {
        v[i] = base[(size_t)(i * 256 + tid) * KK];
        mx = fmaxf(mx, v[i]);
    }
    #pragma unroll
    for (int o = 16; o; o >>= 1) mx = fmaxf(mx, __shfl_xor_sync(0xffffffffu, mx, o));
    if ((tid & 31) == 0) red[tid >> 5] = mx;
    __syncthreads();
    if (tid < 32) {
        float m = (tid < 8) ? red[tid] : -1e30f;
        #pragma unroll
        for (int o = 4; o; o >>= 1) m = fmaxf(m, __shfl_xor_sync(0xffffffffu, m, o));
        if (tid == 0) bcast = m;
    }
    __syncthreads();
    mx = bcast;

    float s = 0.f;
    #pragma unroll
    for (int i = 0; i < 16; ++i) s += __expf(v[i] - mx);
    #pragma unroll
    for (int o = 16; o; o >>= 1) s += __shfl_xor_sync(0xffffffffu, s, o);
    __syncthreads();
    if ((tid & 31) == 0) red[tid >> 5] = s;
    __syncthreads();
    if (tid < 32) {
        float t = (tid < 8) ? red[tid] : 0.f;
        #pragma unroll
        for (int o = 4; o; o >>= 1) t += __shfl_xor_sync(0xffffffffu, t, o);
        if (tid == 0) { g_mx[bk] = mx; g_inv[bk] = 1.0f / t; }
    }
}

// ---------------------------------------------------------------------------
// Kernel 6: out[b,k,c] = sum_n softmax(logits)[b,n,k] * x[b,n,c]
// ---------------------------------------------------------------------------
__global__ __launch_bounds__(256)
void pool_kernel(const float* __restrict__ x, float* __restrict__ out) {
    __shared__ float attn_s[512][8];     // 16 KB
    __shared__ float smx[8], sinv[8];
    const int nc = blockIdx.x;           // 0..7
    const int ct = blockIdx.y;           // 0..2
    const int b  = blockIdx.z;           // 0..31
    const int n0 = nc * 512;
    const int tid = threadIdx.x;

    if (tid < 8) { smx[tid] = g_mx[b * 8 + tid]; sinv[tid] = g_inv[b * 8 + tid]; }
    __syncthreads();

    const float* lp = g_logits + ((size_t)b * NN + n0) * KK;
    for (int i = tid; i < 512 * 8; i += 256) {
        const int k = i & 7;
        attn_s[i >> 3][k] = __expf(lp[i] - smx[k]) * sinv[k];
    }
    __syncthreads();

    const int c = ct * 256 + tid;
    const float* xp = x + ((size_t)b * NN + n0) * CC + c;
    float acc[8];
    #pragma unroll
    for (int kk = 0; kk < 8; ++kk) acc[kk] = 0.f;

    for (int nb = 0; nb < 512; nb += 8) {
        float xv[8];
        #pragma unroll
        for (int u = 0; u < 8; ++u)
            xv[u] = xp[(size_t)(nb + u) * CC];
        #pragma unroll
        for (int u = 0; u < 8; ++u) {
            float4 a0 = *(const float4*)(&attn_s[nb + u][0]);
            float4 a1 = *(const float4*)(&attn_s[nb + u][4]);
            acc[0] = fmaf(a0.x, xv[u], acc[0]);
            acc[1] = fmaf(a0.y, xv[u], acc[1]);
            acc[2] = fmaf(a0.z, xv[u], acc[2]);
            acc[3] = fmaf(a0.w, xv[u], acc[3]);
            acc[4] = fmaf(a1.x, xv[u], acc[4]);
            acc[5] = fmaf(a1.y, xv[u], acc[5]);
            acc[6] = fmaf(a1.z, xv[u], acc[6]);
            acc[7] = fmaf(a1.w, xv[u], acc[7]);
        }
    }
    #pragma unroll
    for (int kk = 0; kk < 8; ++kk)
        atomicAdd(&out[((size_t)b * KK + kk) * CC + c], acc[kk]);
}

// ---------------------------------------------------------------------------
extern "C" void kernel_launch(void* const* d_in, const int* in_sizes, int n_in,
                              void* d_out, int out_size) {
    const float* x     = (const float*)d_in[0];
    const float* gamma = (const float*)d_in[1];
    const float* beta  = (const float*)d_in[2];
    const float* W1    = (const float*)d_in[3];
    const float* b1    = (const float*)d_in[4];
    const float* W2    = (const float*)d_in[5];
    // b2 (d_in[6]) unused: constant over tokens -> cancels in softmax
    float* out = (float*)d_out;

    cudaMemsetAsync(out, 0, (size_t)out_size * sizeof(float));
    ln_convert_kernel<<<MM / 8, 256>>>(x, gamma, beta);                     // 1
    w1_convert_kernel<<<dim3(CC / 32, CC / 32), dim3(32, 8)>>>(W1);         // 2
    zero_logits_kernel<<<(MM * KK) / 1024, 256>>>();                        // 3
    cudaFuncSetAttribute(gemm_kernel, cudaFuncAttributeMaxDynamicSharedMemorySize, SM_TOTAL);
    gemm_kernel<<<dim3(6, MM / 128), NT, SM_TOTAL>>>(W2, b1);               // 4 (profiled)
    softmax_stats_kernel<<<BB * KK, 256>>>();                               // 5
    pool_kernel<<<dim3(8, 3, 32), 256>>>(x, out);                           // 6
}

// round 16
// speedup vs baseline: 1.0069x; 1.0021x over previous
#include <cuda_runtime.h>
#include <cuda_fp16.h>
#include <cstdint>
#include <cstddef>

#define BB 32
#define NN 4096
#define CC 768
#define KK 8
#define MM (BB * NN)   // 131072 rows

// Scratch (__device__ globals; allocation-free rule)
__device__ __half g_A[(size_t)MM * CC];     // LN(x), fp16
__device__ __half g_W1T[(size_t)CC * CC];   // W1^T ([n][k], k contiguous), fp16
__device__ float g_logits[(size_t)MM * KK];
__device__ float g_mx[BB * KK];             // softmax row max per (b,k)
__device__ float g_inv[BB * KK];            // 1/sum per (b,k)

// ---------------------------------------------------------------------------
// PTX helpers (plain-sm_103-legal: mma.sync, ldmatrix, cp.async)
// ---------------------------------------------------------------------------
__device__ __forceinline__ uint32_t smem_to_u32(const void* p) {
    uint32_t a;
    asm("{ .reg .u64 t; cvta.to.shared.u64 t, %1; cvt.u32.u64 %0, t; }"
        : "=r"(a) : "l"(p));
    return a;
}
#define CP_ASYNC16(dst, src) \
    asm volatile("cp.async.cg.shared.global [%0], [%1], 16;" :: "r"(dst), "l"(src))
#define CP_COMMIT() asm volatile("cp.async.commit_group;" ::: "memory")
#define CP_WAIT(n)  asm volatile("cp.async.wait_group %0;" :: "n"(n) : "memory")

__device__ __forceinline__ void ldsm_x4(uint32_t (&r)[4], uint32_t addr) {
    asm volatile("ldmatrix.sync.aligned.m8n8.x4.shared.b16 {%0,%1,%2,%3}, [%4];"
        : "=r"(r[0]), "=r"(r[1]), "=r"(r[2]), "=r"(r[3]) : "r"(addr));
}
__device__ __forceinline__ void mma_f16(float (&d)[4], const uint32_t (&a)[4],
                                        const uint32_t* b) {
    asm volatile(
        "mma.sync.aligned.m16n8k16.row.col.f32.f16.f16.f32 "
        "{%0,%1,%2,%3}, {%4,%5,%6,%7}, {%8,%9}, {%0,%1,%2,%3};"
        : "+f"(d[0]), "+f"(d[1]), "+f"(d[2]), "+f"(d[3])
        : "r"(a[0]), "r"(a[1]), "r"(a[2]), "r"(a[3]), "r"(b[0]), "r"(b[1]));
}

__device__ __forceinline__ float gelu_exact(float v) {
    return 0.5f * v * (1.0f + erff(v * 0.70710678118654752440f));
}

// ---------------------------------------------------------------------------
// Kernel 1: fused LN stats + fp16 convert. One warp per row.
// ---------------------------------------------------------------------------
__global__ __launch_bounds__(256)
void ln_convert_kernel(const float* __restrict__ x,
                       const float* __restrict__ gamma,
                       const float* __restrict__ beta) {
    __shared__ float gs[CC], bs[CC];
    const int tid = threadIdx.x;
    for (int i = tid; i < CC; i += 256) { gs[i] = gamma[i]; bs[i] = beta[i]; }
    __syncthreads();

    const int row  = blockIdx.x * 8 + (tid >> 5);
    const int lane = tid & 31;
    const float4* r = (const float4*)(x + (size_t)row * CC);
    float s = 0.f, ss = 0.f;
    #pragma unroll
    for (int i = lane; i < CC / 4; i += 32) {
        float4 v = r[i];
        s  += v.x + v.y + v.z + v.w;
        ss += v.x * v.x + v.y * v.y + v.z * v.z + v.w * v.w;
    }
    #pragma unroll
    for (int o = 16; o; o >>= 1) {
        s  += __shfl_xor_sync(0xffffffffu, s,  o);
        ss += __shfl_xor_sync(0xffffffffu, ss, o);
    }
    const float mu = s * (1.0f / CC);
    const float rs = rsqrtf(ss * (1.0f / CC) - mu * mu + 1e-5f);

    __half* ap = g_A + (size_t)row * CC;
    #pragma unroll
    for (int i = lane; i < CC / 4; i += 32) {
        float4 v = r[i];
        float y[4] = {v.x, v.y, v.z, v.w};
        union { __half h[4]; uint2 u; } hu;
        #pragma unroll
        for (int j = 0; j < 4; ++j)
            hu.h[j] = __float2half((y[j] - mu) * rs * gs[i * 4 + j] + bs[i * 4 + j]);
        *(uint2*)(ap + i * 4) = hu.u;
    }
}

// ---------------------------------------------------------------------------
// Kernel 2: W1 transpose + fp16 convert. out[n][k] = fp16(W1[k][n]).
// ---------------------------------------------------------------------------
__global__ __launch_bounds__(256)
void w1_convert_kernel(const float* __restrict__ W1) {
    __shared__ float t[32][33];
    const int tx = threadIdx.x, ty = threadIdx.y;    // 32x8
    const int bn = blockIdx.x * 32, bk = blockIdx.y * 32;
    #pragma unroll
    for (int i = 0; i < 4; ++i)
        t[ty + i * 8][tx] = W1[(size_t)(bk + ty + i * 8) * CC + bn + tx];
    __syncthreads();
    #pragma unroll
    for (int i = 0; i < 4; ++i) {
        const int n = bn + ty + i * 8, k = bk + tx;
        g_W1T[(size_t)n * CC + k] = __float2half(t[tx][ty + i * 8]);
    }
}

// ---------------------------------------------------------------------------
// Kernel 3: zero logits (keeps GEMM in ncu's capture slot 4).
// ---------------------------------------------------------------------------
__global__ __launch_bounds__(256)
void zero_logits_kernel() {
    ((float4*)g_logits)[(size_t)blockIdx.x * 256 + threadIdx.x] =
        make_float4(0.f, 0.f, 0.f, 0.f);
}

// ---------------------------------------------------------------------------
// Kernel 4: fp16 mma.sync GEMM  logits += GELU(LN(x)@W1 + b1) @ W2
// CTA tile 128x128, 4 warps (2x2), warp 64x64, KC=64, 3-stage pipeline,
// 2 CTAs/SM. Rows of 128B; swizzle: seg ^= row&7.
// ---------------------------------------------------------------------------
#define KC      64
#define NCH     12                 // 768/64
#define TILE_B  16384              // 128 rows x 128 bytes
#define BUFSZ   (2 * TILE_B)       // A | B = 32KB
#define OFF_B   TILE_B
#define NSTAGE  3
#define SM_W2   (NSTAGE * BUFSZ)   // 98304
#define SM_B1   (SM_W2 + 4096)
#define SM_TOTAL (SM_B1 + 512 + 1024)
#define NT      128                // threads per CTA

__device__ __forceinline__ uint32_t swz(int row, int seg) {
    return (uint32_t)(row * 128) + (uint32_t)(((seg ^ (row & 7)) & 7) << 4);
}

__device__ __forceinline__ void load_tile_cp(uint32_t dst, const __half* src,
                                             int tid) {
    // 128 rows x 64 fp16 (128B rows) = 1024 x 16B, 8 per thread
    #pragma unroll
    for (int j = 0; j < 8; ++j) {
        const int c = tid + j * NT;
        const int row = c >> 3, seg = c & 7;
        CP_ASYNC16(dst + swz(row, seg), src + (size_t)row * CC + seg * 8);
    }
}

__global__ __launch_bounds__(NT, 2)
void gemm_kernel(const float* __restrict__ W2, const float* __restrict__ b1) {
    extern __shared__ __align__(16) char smraw[];
    const uint32_t sbraw = smem_to_u32(smraw);
    const uint32_t sb = (sbraw + 1023u) & ~1023u;
    char* sm = smraw + (sb - sbraw);
    float* W2s = (float*)(sm + SM_W2);
    float* b1s = (float*)(sm + SM_B1);

    const int tid = threadIdx.x;
    const int wid = tid >> 5;
    const int lid = tid & 31;
    const int warp_m = wid & 1;          // 2 along M (64 rows each)
    const int warp_n = wid >> 1;         // 2 along N (64 cols each)
    const int n0 = blockIdx.x * 128;
    const int r0 = blockIdx.y * 128;

    const __half* pA = g_A   + (size_t)r0 * CC;
    const __half* pB = g_W1T + (size_t)n0 * CC;

    for (int i = tid; i < 1024; i += NT) W2s[i] = W2[(size_t)n0 * KK + i];
    if (tid < 128) b1s[tid] = b1[n0 + tid];

    // prologue: stages 0, 1
    #pragma unroll
    for (int st = 0; st < 2; ++st) {
        const uint32_t bb = sb + st * BUFSZ;
        const int k0 = st * KC;
        load_tile_cp(bb,         pA + k0, tid);
        load_tile_cp(bb + OFF_B, pB + k0, tid);
        CP_COMMIT();
    }

    float acc[4][8][4];                  // mf(4 x m16) x nf(8 x n8) x 4
    #pragma unroll
    for (int mf = 0; mf < 4; ++mf)
        #pragma unroll
        for (int nf = 0; nf < 8; ++nf)
            #pragma unroll
            for (int r = 0; r < 4; ++r) acc[mf][nf][r] = 0.f;

    const int a_row = warp_m * 64 + (lid & 15);                       // + mf*16
    const int a_seg = lid >> 4;                                       // + ks*2
    const int b_mat = lid >> 3;
    const int b_row = warp_n * 64 + ((b_mat >> 1) << 3) + (lid & 7);  // + np*16
    const int b_seg = b_mat & 1;                                      // + ks*2

    int stage = 0;
    for (int i = 0; i < NCH; ++i) {
        if (i < NCH - 1) CP_WAIT(1); else CP_WAIT(0);
        __syncthreads();

        // prefetch stage i+2 (overwrites buffer of stage i-1; safe after sync)
        if (i + 2 < NCH) {
            int st2 = stage + 2; if (st2 >= NSTAGE) st2 -= NSTAGE;
            const uint32_t bb = sb + st2 * BUFSZ;
            const int k0 = (i + 2) * KC;
            load_tile_cp(bb,         pA + k0, tid);
            load_tile_cp(bb + OFF_B, pB + k0, tid);
            CP_COMMIT();
        }

        const uint32_t bb = sb + stage * BUFSZ;
        #pragma unroll
        for (int ks = 0; ks < 4; ++ks) {
            uint32_t af[4][4];
            #pragma unroll
            for (int mf = 0; mf < 4; ++mf)
                ldsm_x4(af[mf], bb + swz(a_row + mf * 16, a_seg + ks * 2));
            #pragma unroll
            for (int np = 0; np < 4; ++np) {
                uint32_t bf[4];
                ldsm_x4(bf, bb + OFF_B + swz(b_row + np * 16, b_seg + ks * 2));
                #pragma unroll
                for (int mf = 0; mf < 4; ++mf) {
                    mma_f16(acc[mf][np * 2 + 0], af[mf], bf + 0);
                    mma_f16(acc[mf][np * 2 + 1], af[mf], bf + 2);
                }
            }
        }
        ++stage; if (stage == NSTAGE) stage = 0;
    }
    __syncthreads();

    // ---------------- Epilogue: +b1, GELU, fold W2, reduce ----------------
    float* logits_s = (float*)sm;        // reuse pipeline smem: 128x8 f32
    for (int i = tid; i < 1024; i += NT) logits_s[i] = 0.f;
    __syncthreads();

    const int qr = lid >> 2, qc = lid & 3;
    #pragma unroll
    for (int mf = 0; mf < 4; ++mf) {
        float lg[2][8];
        #pragma unroll
        for (int h = 0; h < 2; ++h)
            #pragma unroll
            for (int k = 0; k < 8; ++k) lg[h][k] = 0.f;

        #pragma unroll
        for (int nf = 0; nf < 8; ++nf) {
            const int colb = warp_n * 64 + nf * 8 + qc * 2;
            #pragma unroll
            for (int r = 0; r < 4; ++r) {
                const int c = colb + (r & 1);
                const float v = acc[mf][nf][r] + b1s[c];
                const float hh = gelu_exact(v);
                const float* w = &W2s[c * 8];
                float* l = lg[r >> 1];
                #pragma unroll
                for (int k = 0; k < 8; ++k) l[k] = fmaf(hh, w[k], l[k]);
            }
        }
        const int rA = warp_m * 64 + mf * 16 + qr;
        #pragma unroll
        for (int k = 0; k < 8; ++k) {
            atomicAdd(&logits_s[rA * 8 + k],       lg[0][k]);
            atomicAdd(&logits_s[(rA + 8) * 8 + k], lg[1][k]);
        }
    }
    __syncthreads();

    for (int i = tid; i < 1024; i += NT) {
        const int r = i >> 3, k = i & 7;
        atomicAdd(&g_logits[(size_t)(r0 + r) * KK + k], logits_s[i]);
    }
}

// ---------------------------------------------------------------------------
// Kernel 5: softmax stats per (b,k): row max and 1/sum(exp).
// ---------------------------------------------------------------------------
__global__ __launch_bounds__(256)
void softmax_stats_kernel() {
    __shared__ float red[8];
    __shared__ float bcast;
    const int bk = blockIdx.x;
    const int b  = bk >> 3;
    const int kk = bk & 7;
    const int tid = threadIdx.x;
    const float* base = g_logits + (size_t)b * NN * KK + kk;

    float v[16];
    float mx = -1e30f;
    #pragma unroll
    for (int i = 0; i < 16; ++i) {
        v[i] = base[(size_t)(i * 256 + tid) * KK];
        mx = fmaxf(mx, v[i]);
    }
    #pragma unroll
    for (int o = 16; o; o >>= 1) mx = fmaxf(mx, __shfl_xor_sync(0xffffffffu, mx, o));
    if ((tid & 31) == 0) red[tid >> 5] = mx;
    __syncthreads();
    if (tid < 32) {
        float m = (tid < 8) ? red[tid] : -1e30f;
        #pragma unroll
        for (int o = 4; o; o >>= 1) m = fmaxf(m, __shfl_xor_sync(0xffffffffu, m, o));
        if (tid == 0) bcast = m;
    }
    __syncthreads();
    mx = bcast;

    float s = 0.f;
    #pragma unroll
    for (int i = 0; i < 16; ++i) s += __expf(v[i] - mx);
    #pragma unroll
    for (int o = 16; o; o >>= 1) s += __shfl_xor_sync(0xffffffffu, s, o);
    __syncthreads();
    if ((tid & 31) == 0) red[tid >> 5] = s;
    __syncthreads();
    if (tid < 32) {
        float t = (tid < 8) ? red[tid] : 0.f;
        #pragma unroll
        for (int o = 4; o; o >>= 1) t += __shfl_xor_sync(0xffffffffu, t, o);
        if (tid == 0) { g_mx[bk] = mx; g_inv[bk] = 1.0f / t; }
    }
}

// ---------------------------------------------------------------------------
// Kernel 6: out[b,k,c] = sum_n softmax(logits)[b,n,k] * x[b,n,c]
// ---------------------------------------------------------------------------
__global__ __launch_bounds__(256)
void pool_kernel(const float* __restrict__ x, float* __restrict__ out) {
    __shared__ float attn_s[512][8];     // 16 KB
    __shared__ float smx[8], sinv[8];
    const int nc = blockIdx.x;           // 0..7
    const int ct = blockIdx.y;           // 0..2
    const int b  = blockIdx.z;           // 0..31
    const int n0 = nc * 512;
    const int tid = threadIdx.x;

    if (tid < 8) { smx[tid] = g_mx[b * 8 + tid]; sinv[tid] = g_inv[b * 8 + tid]; }
    __syncthreads();

    const float* lp = g_logits + ((size_t)b * NN + n0) * KK;
    for (int i = tid; i < 512 * 8; i += 256) {
        const int k = i & 7;
        attn_s[i >> 3][k] = __expf(lp[i] - smx[k]) * sinv[k];
    }
    __syncthreads();

    const int c = ct * 256 + tid;
    const float* xp = x + ((size_t)b * NN + n0) * CC + c;
    float acc[8];
    #pragma unroll
    for (int kk = 0; kk < 8; ++kk) acc[kk] = 0.f;

    for (int nb = 0; nb < 512; nb += 8) {
        float xv[8];
        #pragma unroll
        for (int u = 0; u < 8; ++u)
            xv[u] = xp[(size_t)(nb + u) * CC];
        #pragma unroll
        for (int u = 0; u < 8; ++u) {
            float4 a0 = *(const float4*)(&attn_s[nb + u][0]);
            float4 a1 = *(const float4*)(&attn_s[nb + u][4]);
            acc[0] = fmaf(a0.x, xv[u], acc[0]);
            acc[1] = fmaf(a0.y, xv[u], acc[1]);
            acc[2] = fmaf(a0.z, xv[u], acc[2]);
            acc[3] = fmaf(a0.w, xv[u], acc[3]);
            acc[4] = fmaf(a1.x, xv[u], acc[4]);
            acc[5] = fmaf(a1.y, xv[u], acc[5]);
            acc[6] = fmaf(a1.z, xv[u], acc[6]);
            acc[7] = fmaf(a1.w, xv[u], acc[7]);
        }
    }
    #pragma unroll
    for (int kk = 0; kk < 8; ++kk)
        atomicAdd(&out[((size_t)b * KK + kk) * CC + c], acc[kk]);
}

// ---------------------------------------------------------------------------
extern "C" void kernel_launch(void* const* d_in, const int* in_sizes, int n_in,
                              void* d_out, int out_size) {
    const float* x     = (const float*)d_in[0];
    const float* gamma = (const float*)d_in[1];
    const float* beta  = (const float*)d_in[2];
    const float* W1    = (const float*)d_in[3];
    const float* b1    = (const float*)d_in[4];
    const float* W2    = (const float*)d_in[5];
    // b2 (d_in[6]) unused: constant over tokens -> cancels in softmax
    float* out = (float*)d_out;

    cudaMemsetAsync(out, 0, (size_t)out_size * sizeof(float));
    ln_convert_kernel<<<MM / 8, 256>>>(x, gamma, beta);                     // 1
    w1_convert_kernel<<<dim3(CC / 32, CC / 32), dim3(32, 8)>>>(W1);         // 2
    zero_logits_kernel<<<(MM * KK) / 1024, 256>>>();                        // 3
    cudaFuncSetAttribute(gemm_kernel, cudaFuncAttributeMaxDynamicSharedMemorySize, SM_TOTAL);
    gemm_kernel<<<dim3(6, MM / 128), NT, SM_TOTAL>>>(W2, b1);               // 4 (profiled)
    softmax_stats_kernel<<<BB * KK, 256>>>();                               // 5
    pool_kernel<<<dim3(8, 3, 32), 256>>>(x, out);                           // 6
}